// round 1
// baseline (speedup 1.0000x reference)
#include <cuda_runtime.h>
#include <cstdint>

#define BB 8
#define TQ 128
#define TK 128
#define NH 512
#define UNITS 256
// 2 * log2(e): folded into projections so EX2 input is just (q2 + k2)
#define C2LOG2E 2.8853900817779268f

// scratch (allocation-free rule: device globals)
__device__ float g_q2[BB * TQ * UNITS];
__device__ float g_k2[BB * TK * UNITS];

__device__ __forceinline__ float ex2a(float x) {
    float y; asm("ex2.approx.f32 %0, %1;" : "=f"(y) : "f"(x)); return y;
}
__device__ __forceinline__ float rcpa(float x) {
    float y; asm("rcp.approx.f32 %0, %1;" : "=f"(y) : "f"(x)); return y;
}

// ---------------------------------------------------------------------------
// Kernel 1: projections.  Y[m][n] = C2LOG2E * sum_k X[m][k] * W[k][n]
// M = 1024 (B*T), K = 512 (NH), N = 256 (UNITS).  z=0: query*W1 -> g_q2,
// z=1: value*W2 -> g_k2.  64x64 block tile, 4x4 per thread, BK=16.
// ---------------------------------------------------------------------------
#define PBM 64
#define PBN 64
#define PBK 16

__global__ __launch_bounds__(256) void proj_kernel(
    const float* __restrict__ Q, const float* __restrict__ V,
    const float* __restrict__ W1, const float* __restrict__ W2)
{
    const int z = blockIdx.z;
    const float* __restrict__ X = z ? V : Q;
    const float* __restrict__ W = z ? W2 : W1;
    float* __restrict__ Y = z ? g_k2 : g_q2;

    __shared__ float As[PBK][PBM];       // [k][m] transposed A tile
    __shared__ float Bs[PBK][PBN + 4];   // padded, keeps float4 alignment

    const int tid = threadIdx.x;
    const int tx = tid & 15;             // n micro-tile index
    const int ty = tid >> 4;             // m micro-tile index
    const int m0 = blockIdx.y * PBM;
    const int n0 = blockIdx.x * PBN;

    // A-tile load mapping: 64 rows x 16 k, float4 along k
    const int ar  = tid >> 2;            // 0..63
    const int ac4 = (tid & 3) << 2;      // 0,4,8,12
    // B-tile load mapping: 16 k-rows x 64 n, float4 along n
    const int br  = tid >> 4;            // 0..15
    const int bc4 = (tid & 15) << 2;     // 0..60

    float acc[4][4] = {};

    for (int k0 = 0; k0 < NH; k0 += PBK) {
        float4 av = *reinterpret_cast<const float4*>(&X[(m0 + ar) * NH + k0 + ac4]);
        float4 bv = *reinterpret_cast<const float4*>(&W[(k0 + br) * UNITS + n0 + bc4]);
        __syncthreads();   // previous tile fully consumed
        As[ac4 + 0][ar] = av.x;
        As[ac4 + 1][ar] = av.y;
        As[ac4 + 2][ar] = av.z;
        As[ac4 + 3][ar] = av.w;
        *reinterpret_cast<float4*>(&Bs[br][bc4]) = bv;
        __syncthreads();
        #pragma unroll
        for (int kk = 0; kk < PBK; kk++) {
            float4 a = *reinterpret_cast<const float4*>(&As[kk][ty * 4]);
            float4 b = *reinterpret_cast<const float4*>(&Bs[kk][tx * 4]);
            float ax[4] = {a.x, a.y, a.z, a.w};
            float bx[4] = {b.x, b.y, b.z, b.w};
            #pragma unroll
            for (int i = 0; i < 4; i++)
                #pragma unroll
                for (int j = 0; j < 4; j++)
                    acc[i][j] = fmaf(ax[i], bx[j], acc[i][j]);
        }
    }

    #pragma unroll
    for (int i = 0; i < 4; i++) {
        float4 o;
        o.x = acc[i][0] * C2LOG2E;
        o.y = acc[i][1] * C2LOG2E;
        o.z = acc[i][2] * C2LOG2E;
        o.w = acc[i][3] * C2LOG2E;
        *reinterpret_cast<float4*>(&Y[(m0 + ty * 4 + i) * UNITS + n0 + tx * 4]) = o;
    }
}

// ---------------------------------------------------------------------------
// Kernel 2: scores (tanh via ex2+rcp) + masked softmax + context + attn out.
// Grid: (TQ/TT, B) = (16, 8) blocks, 512 threads.
// Each block: 8 queries x 128 keys. Each thread owns 2 (t,s) pairs.
// score = sum_u scale_u * tanh(q+k) = (sum_u scale_u) - 2*sum_u scale_u/(e^{2(q+k)}+1)
// ---------------------------------------------------------------------------
#define TT  8
#define UC  64
#define NT2 512

__global__ __launch_bounds__(NT2) void attn_kernel(
    const float* __restrict__ value,
    const void*  __restrict__ maskp,
    const float* __restrict__ scale,
    float* __restrict__ out)
{
    __shared__ float kc[TK][UC + 1];     // 33280 B, bank-conflict-free on s
    __shared__ float qc[TT][UC + 1];
    __shared__ float sc[UC];
    __shared__ float sco[TT][TK];        // scores -> attn weights

    const int tid = threadIdx.x;
    const int b   = blockIdx.y;
    const int t0  = blockIdx.x * TT;

    const int s_a = tid & 127;           // key index for both pairs
    const int t_a = tid >> 7;            // 0..3
    const int t_b = t_a + 4;             // 4..7

    float acc0 = 0.f, acc1 = 0.f, accS = 0.f;

    for (int u0 = 0; u0 < UNITS; u0 += UC) {
        __syncthreads();
        // stage k2 chunk: 128 x 64 floats (512 float4s per 2 threads)
        #pragma unroll
        for (int i = 0; i < 4; i++) {
            int idx = tid + i * NT2;              // float4 index, 0..2047
            int s   = idx >> 4;
            int u4  = (idx & 15) << 2;
            float4 v = *reinterpret_cast<const float4*>(
                &g_k2[(b * TK + s) * UNITS + u0 + u4]);
            kc[s][u4 + 0] = v.x; kc[s][u4 + 1] = v.y;
            kc[s][u4 + 2] = v.z; kc[s][u4 + 3] = v.w;
        }
        // stage q2 chunk: 8 x 64
        {
            int t = tid >> 6;                     // 0..7
            int u = tid & 63;
            qc[t][u] = g_q2[(b * TQ + t0 + t) * UNITS + u0 + u];
        }
        if (tid < UC) sc[tid] = scale[u0 + tid];
        __syncthreads();

        #pragma unroll 4
        for (int u = 0; u < UC; u++) {
            float sv = sc[u];
            float kv = kc[s_a][u];
            float x0 = qc[t_a][u] + kv;           // already * 2*log2(e)
            float x1 = qc[t_b][u] + kv;
            float e0 = ex2a(x0);
            float e1 = ex2a(x1);
            float r0 = rcpa(e0 + 1.0f);
            float r1 = rcpa(e1 + 1.0f);
            acc0 = fmaf(sv, r0, acc0);
            acc1 = fmaf(sv, r1, acc1);
            accS += sv;
        }
    }

    // mask layout discriminator (lengths >= 64 => mask[0][0..3] all true)
    const unsigned int tag = *reinterpret_cast<const unsigned int*>(maskp);
    bool valid;
    if (tag == 1u) {
        valid = reinterpret_cast<const int*>(maskp)[b * TK + s_a] != 0;
    } else if (tag == 0x3f800000u) {
        valid = reinterpret_cast<const float*>(maskp)[b * TK + s_a] != 0.0f;
    } else {
        valid = reinterpret_cast<const unsigned char*>(maskp)[b * TK + s_a] != 0;
    }

    float score0 = accS - 2.0f * acc0;
    float score1 = accS - 2.0f * acc1;
    sco[t_a][s_a] = valid ? score0 : -1e9f;
    sco[t_b][s_a] = valid ? score1 : -1e9f;
    __syncthreads();

    // masked softmax: one warp per query row
    const int wid  = tid >> 5;
    const int lane = tid & 31;
    if (wid < TT) {
        float v0 = sco[wid][lane +  0];
        float v1 = sco[wid][lane + 32];
        float v2 = sco[wid][lane + 64];
        float v3 = sco[wid][lane + 96];
        float m = fmaxf(fmaxf(v0, v1), fmaxf(v2, v3));
        #pragma unroll
        for (int o = 16; o; o >>= 1) m = fmaxf(m, __shfl_xor_sync(0xffffffffu, m, o));
        float e0 = __expf(v0 - m), e1 = __expf(v1 - m);
        float e2 = __expf(v2 - m), e3 = __expf(v3 - m);
        float s = e0 + e1 + e2 + e3;
        #pragma unroll
        for (int o = 16; o; o >>= 1) s += __shfl_xor_sync(0xffffffffu, s, o);
        float inv = 1.0f / s;
        e0 *= inv; e1 *= inv; e2 *= inv; e3 *= inv;
        sco[wid][lane +  0] = e0;
        sco[wid][lane + 32] = e1;
        sco[wid][lane + 64] = e2;
        sco[wid][lane + 96] = e3;
        float* aout = out + (size_t)BB * TQ * NH + (size_t)(b * TQ + t0 + wid) * TK;
        aout[lane +  0] = e0;
        aout[lane + 32] = e1;
        aout[lane + 64] = e2;
        aout[lane + 96] = e3;
    }
    __syncthreads();

    // context: thread tid owns feature h = tid for all TT queries
    float ctx[TT] = {};
    const float* vb = value + (size_t)b * TK * NH + tid;
    #pragma unroll 2
    for (int s = 0; s < TK; s++) {
        float v = __ldg(vb + s * NH);
        #pragma unroll
        for (int t = 0; t < TT; t++)
            ctx[t] = fmaf(sco[t][s], v, ctx[t]);
    }
    float* cout = out + (size_t)(b * TQ + t0) * NH + tid;
    #pragma unroll
    for (int t = 0; t < TT; t++) cout[t * NH] = ctx[t];
}

// ---------------------------------------------------------------------------
extern "C" void kernel_launch(void* const* d_in, const int* in_sizes, int n_in,
                              void* d_out, int out_size)
{
    const float* query = (const float*)d_in[0];   // (B,TQ,NH)
    const float* value = (const float*)d_in[1];   // (B,TK,NH)
    const void*  mask  = d_in[2];                 // (B,TK) bool (layout sniffed)
    const float* W1    = (const float*)d_in[3];   // (NH,UNITS)
    const float* W2    = (const float*)d_in[4];   // (NH,UNITS)
    const float* scale = (const float*)d_in[5];   // (UNITS,)
    float* out = (float*)d_out;                   // [context | attn]

    dim3 g1(UNITS / PBN, (BB * TQ) / PBM, 2);     // (4,16,2) = 128 blocks
    proj_kernel<<<g1, 256>>>(query, value, W1, W2);

    dim3 g2(TQ / TT, BB);                         // (16,8) = 128 blocks
    attn_kernel<<<g2, NT2>>>(value, mask, scale, out);
}

// round 2
// speedup vs baseline: 1.1392x; 1.1392x over previous
#include <cuda_runtime.h>
#include <cstdint>

#define BB 8
#define TQ 128
#define TK 128
#define NH 512
#define UNITS 256
// 2 * log2(e): folded into projections so EX2 input is just (q2 + k2)
#define C2LOG2E 2.8853900817779268f

// scratch (allocation-free rule: device globals)
__device__ float g_q2[BB * TQ * UNITS];
__device__ float g_k2[BB * TK * UNITS];

__device__ __forceinline__ float ex2a(float x) {
    float y; asm("ex2.approx.f32 %0, %1;" : "=f"(y) : "f"(x)); return y;
}
__device__ __forceinline__ float rcpa(float x) {
    float y; asm("rcp.approx.f32 %0, %1;" : "=f"(y) : "f"(x)); return y;
}

// ---------------------------------------------------------------------------
// Kernel 1: projections.  Y[m][n] = C2LOG2E * sum_k X[m][k] * W[k][n]
// M = 1024 (B*T), K = 512 (NH), N = 256 (UNITS).  z=0: query*W1 -> g_q2,
// z=1: value*W2 -> g_k2.  64x64 block tile, 4x4 per thread, BK=16.
// ---------------------------------------------------------------------------
#define PBM 64
#define PBN 64
#define PBK 16

__global__ __launch_bounds__(256) void proj_kernel(
    const float* __restrict__ Q, const float* __restrict__ V,
    const float* __restrict__ W1, const float* __restrict__ W2)
{
    const int z = blockIdx.z;
    const float* __restrict__ X = z ? V : Q;
    const float* __restrict__ W = z ? W2 : W1;
    float* __restrict__ Y = z ? g_k2 : g_q2;

    __shared__ float As[PBK][PBM];       // [k][m] transposed A tile
    __shared__ float Bs[PBK][PBN + 4];   // padded, keeps float4 alignment

    const int tid = threadIdx.x;
    const int tx = tid & 15;             // n micro-tile index
    const int ty = tid >> 4;             // m micro-tile index
    const int m0 = blockIdx.y * PBM;
    const int n0 = blockIdx.x * PBN;

    const int ar  = tid >> 2;            // 0..63
    const int ac4 = (tid & 3) << 2;      // 0,4,8,12
    const int br  = tid >> 4;            // 0..15
    const int bc4 = (tid & 15) << 2;     // 0..60

    float acc[4][4] = {};

    for (int k0 = 0; k0 < NH; k0 += PBK) {
        float4 av = *reinterpret_cast<const float4*>(&X[(m0 + ar) * NH + k0 + ac4]);
        float4 bv = *reinterpret_cast<const float4*>(&W[(k0 + br) * UNITS + n0 + bc4]);
        __syncthreads();
        As[ac4 + 0][ar] = av.x;
        As[ac4 + 1][ar] = av.y;
        As[ac4 + 2][ar] = av.z;
        As[ac4 + 3][ar] = av.w;
        *reinterpret_cast<float4*>(&Bs[br][bc4]) = bv;
        __syncthreads();
        #pragma unroll
        for (int kk = 0; kk < PBK; kk++) {
            float4 a = *reinterpret_cast<const float4*>(&As[kk][ty * 4]);
            float4 b = *reinterpret_cast<const float4*>(&Bs[kk][tx * 4]);
            float ax[4] = {a.x, a.y, a.z, a.w};
            float bx[4] = {b.x, b.y, b.z, b.w};
            #pragma unroll
            for (int i = 0; i < 4; i++)
                #pragma unroll
                for (int j = 0; j < 4; j++)
                    acc[i][j] = fmaf(ax[i], bx[j], acc[i][j]);
        }
    }

    #pragma unroll
    for (int i = 0; i < 4; i++) {
        float4 o;
        o.x = acc[i][0] * C2LOG2E;
        o.y = acc[i][1] * C2LOG2E;
        o.z = acc[i][2] * C2LOG2E;
        o.w = acc[i][3] * C2LOG2E;
        *reinterpret_cast<float4*>(&Y[(m0 + ty * 4 + i) * UNITS + n0 + tx * 4]) = o;
    }
}

// ---------------------------------------------------------------------------
// Kernel 2: scores + masked softmax + context + attn out.
// Grid: (TQ/TT, B) = (32, 8) = 256 blocks, 256 threads each.
// Block: TT=4 queries x 128 keys. Thread: 2 (t,s) elements sharing one rcp.
// score = sSum - 2 * sum_u scale_u / (e^{2(q+k)} + 1)
// ---------------------------------------------------------------------------
#define TT  4
#define UC  64
#define UC4 (UC/4)
#define NT2 256

__global__ __launch_bounds__(NT2, 2) void attn_kernel(
    const float* __restrict__ value,
    const void*  __restrict__ maskp,
    const float* __restrict__ scale,
    float* __restrict__ out)
{
    __shared__ float4 kc4[TK][UC4 + 1];   // stride 17 float4 -> conflict-free
    __shared__ float4 qc4[TT][UC4 + 1];
    __shared__ float4 sc4[UC4];
    __shared__ float  sco[TT][TK];
    __shared__ float  red[8];
    __shared__ float  sSumSh;

    const int tid = threadIdx.x;
    const int b   = blockIdx.y;
    const int t0  = blockIdx.x * TT;

    const int s_ = tid & 127;
    const int tg = tid >> 7;             // 0..1
    const int ta = tg * 2;
    const int tb = ta + 1;

    // ---- sum of scale (once) ----
    {
        float v = scale[tid];            // UNITS == NT2 == 256
        #pragma unroll
        for (int o = 16; o; o >>= 1) v += __shfl_xor_sync(0xffffffffu, v, o);
        if ((tid & 31) == 0) red[tid >> 5] = v;
    }

    // ---- mask (layout sniffed; lengths >= 64 so word 0 is a valid tag) ----
    const unsigned int tag = *reinterpret_cast<const unsigned int*>(maskp);
    bool valid;
    if (tag == 1u) {
        valid = reinterpret_cast<const int*>(maskp)[b * TK + s_] != 0;
    } else if (tag == 0x3f800000u) {
        valid = reinterpret_cast<const float*>(maskp)[b * TK + s_] != 0.0f;
    } else {
        valid = reinterpret_cast<const unsigned char*>(maskp)[b * TK + s_] != 0;
    }

    const float4* __restrict__ k2v = reinterpret_cast<const float4*>(g_k2);
    const float4* __restrict__ q2v = reinterpret_cast<const float4*>(g_q2);
    const float4* __restrict__ sclv = reinterpret_cast<const float4*>(scale);

    // prefetch chunk 0 of k into registers
    float4 pre[8];
    #pragma unroll
    for (int i = 0; i < 8; i++) {
        int idx = tid + i * NT2;
        int s   = idx >> 4;
        int u4  = idx & 15;
        pre[i] = k2v[(b * TK + s) * (UNITS/4) + u4];
    }

    float acc0 = 0.f, acc1 = 0.f;

    for (int c = 0; c < UNITS / UC; c++) {
        const int u0_4 = c * UC4;
        __syncthreads();                 // prev chunk consumed / red[] ready
        if (c == 0 && tid == 0) {
            float s8 = 0.f;
            #pragma unroll
            for (int i = 0; i < 8; i++) s8 += red[i];
            sSumSh = s8;
        }
        #pragma unroll
        for (int i = 0; i < 8; i++) {
            int idx = tid + i * NT2;
            kc4[idx >> 4][idx & 15] = pre[i];
        }
        if (tid < TT * UC4) {
            int t  = tid >> 4;
            int u4 = tid & 15;
            qc4[t][u4] = q2v[(b * TQ + t0 + t) * (UNITS/4) + u0_4 + u4];
        }
        if (tid < UC4) sc4[tid] = sclv[u0_4 + tid];
        __syncthreads();

        if (c < UNITS / UC - 1) {        // prefetch next chunk during compute
            #pragma unroll
            for (int i = 0; i < 8; i++) {
                int idx = tid + i * NT2;
                int s   = idx >> 4;
                int u4  = idx & 15;
                pre[i] = k2v[(b * TK + s) * (UNITS/4) + u0_4 + UC4 + u4];
            }
        }

        #pragma unroll
        for (int u4 = 0; u4 < UC4; u4++) {
            float4 kv = kc4[s_][u4];
            float4 qa = qc4[ta][u4];     // broadcast (ta uniform per warp)
            float4 qb = qc4[tb][u4];
            float4 sv = sc4[u4];
            #define DOC(C) { \
                float e0 = ex2a(qa.C + kv.C); \
                float e1 = ex2a(qb.C + kv.C); \
                float A = e0 + 1.0f, Bv = e1 + 1.0f; \
                float r = rcpa(A * Bv); \
                acc0 = fmaf(sv.C, r * Bv, acc0); \
                acc1 = fmaf(sv.C, r * A,  acc1); }
            DOC(x) DOC(y) DOC(z) DOC(w)
            #undef DOC
        }
    }

    const float sSum = sSumSh;
    float score0 = sSum - 2.0f * acc0;
    float score1 = sSum - 2.0f * acc1;
    sco[ta][s_] = valid ? score0 : -1e9f;
    sco[tb][s_] = valid ? score1 : -1e9f;
    __syncthreads();

    // ---- masked softmax: one warp per query row (warps 0..3) ----
    const int wid  = tid >> 5;
    const int lane = tid & 31;
    if (wid < TT) {
        float v0 = sco[wid][lane +  0];
        float v1 = sco[wid][lane + 32];
        float v2 = sco[wid][lane + 64];
        float v3 = sco[wid][lane + 96];
        float m = fmaxf(fmaxf(v0, v1), fmaxf(v2, v3));
        #pragma unroll
        for (int o = 16; o; o >>= 1) m = fmaxf(m, __shfl_xor_sync(0xffffffffu, m, o));
        float e0 = __expf(v0 - m), e1 = __expf(v1 - m);
        float e2 = __expf(v2 - m), e3 = __expf(v3 - m);
        float s = e0 + e1 + e2 + e3;
        #pragma unroll
        for (int o = 16; o; o >>= 1) s += __shfl_xor_sync(0xffffffffu, s, o);
        float inv = 1.0f / s;
        e0 *= inv; e1 *= inv; e2 *= inv; e3 *= inv;
        sco[wid][lane +  0] = e0;
        sco[wid][lane + 32] = e1;
        sco[wid][lane + 64] = e2;
        sco[wid][lane + 96] = e3;
        float* aout = out + (size_t)BB * TQ * NH + (size_t)(b * TQ + t0 + wid) * TK;
        aout[lane +  0] = e0;
        aout[lane + 32] = e1;
        aout[lane + 64] = e2;
        aout[lane + 96] = e3;
    }
    __syncthreads();

    // ---- context: thread owns features tid and tid+256 for all TT queries ----
    float ctx[TT][2] = {};
    const float* vb = value + (size_t)b * TK * NH;
    #pragma unroll 4
    for (int s = 0; s < TK; s++) {
        float v0 = __ldg(vb + (size_t)s * NH + tid);
        float v1 = __ldg(vb + (size_t)s * NH + tid + 256);
        #pragma unroll
        for (int t = 0; t < TT; t++) {
            float w = sco[t][s];
            ctx[t][0] = fmaf(w, v0, ctx[t][0]);
            ctx[t][1] = fmaf(w, v1, ctx[t][1]);
        }
    }
    #pragma unroll
    for (int t = 0; t < TT; t++) {
        float* cout = out + (size_t)(b * TQ + t0 + t) * NH;
        cout[tid]       = ctx[t][0];
        cout[tid + 256] = ctx[t][1];
    }
}

// ---------------------------------------------------------------------------
extern "C" void kernel_launch(void* const* d_in, const int* in_sizes, int n_in,
                              void* d_out, int out_size)
{
    const float* query = (const float*)d_in[0];   // (B,TQ,NH)
    const float* value = (const float*)d_in[1];   // (B,TK,NH)
    const void*  mask  = d_in[2];                 // (B,TK) bool (layout sniffed)
    const float* W1    = (const float*)d_in[3];   // (NH,UNITS)
    const float* W2    = (const float*)d_in[4];   // (NH,UNITS)
    const float* scale = (const float*)d_in[5];   // (UNITS,)
    float* out = (float*)d_out;                   // [context | attn]

    dim3 g1(UNITS / PBN, (BB * TQ) / PBM, 2);     // (4,16,2) = 128 blocks
    proj_kernel<<<g1, 256>>>(query, value, W1, W2);

    dim3 g2(TQ / TT, BB);                         // (32,8) = 256 blocks
    attn_kernel<<<g2, NT2>>>(value, mask, scale, out);
}

// round 4
// speedup vs baseline: 1.1422x; 1.0027x over previous
#include <cuda_runtime.h>
#include <cstdint>

#define BB 8
#define TQ 128
#define TK 128
#define NH 512
#define UNITS 256

// scratch (allocation-free rule: device globals)
__device__ float g_q2[BB * TQ * UNITS];          // [b][t][u]
__device__ float g_k2t[BB * UNITS * TK];         // [b][u][s]  (transposed!)

__device__ __forceinline__ float tanha(float x) {
    float y; asm("tanh.approx.f32 %0, %1;" : "=f"(y) : "f"(x)); return y;
}

// ---------------------------------------------------------------------------
// Kernel 1: projections.  q = query@W1 -> g_q2 [b][t][u]
//                         k = value@W2 -> g_k2t [b][u][s] (transposed store)
// M = 1024 (B*T), K = 512 (NH), N = 256 (UNITS). 64x64 tile, 4x4/thread.
// ---------------------------------------------------------------------------
#define PBM 64
#define PBN 64
#define PBK 16

__global__ __launch_bounds__(256) void proj_kernel(
    const float* __restrict__ Q, const float* __restrict__ V,
    const float* __restrict__ W1, const float* __restrict__ W2)
{
    const int z = blockIdx.z;
    const float* __restrict__ X = z ? V : Q;
    const float* __restrict__ W = z ? W2 : W1;

    __shared__ float As[PBK][PBM];
    __shared__ float Bs[PBK][PBN + 4];
    __shared__ float Cs[PBN][PBM + 1];   // transpose staging (z==1 only)

    const int tid = threadIdx.x;
    const int tx = tid & 15;
    const int ty = tid >> 4;
    const int m0 = blockIdx.y * PBM;
    const int n0 = blockIdx.x * PBN;

    const int ar  = tid >> 2;
    const int ac4 = (tid & 3) << 2;
    const int br  = tid >> 4;
    const int bc4 = (tid & 15) << 2;

    float acc[4][4] = {};

    for (int k0 = 0; k0 < NH; k0 += PBK) {
        float4 av = *reinterpret_cast<const float4*>(&X[(m0 + ar) * NH + k0 + ac4]);
        float4 bv = *reinterpret_cast<const float4*>(&W[(k0 + br) * UNITS + n0 + bc4]);
        __syncthreads();
        As[ac4 + 0][ar] = av.x;
        As[ac4 + 1][ar] = av.y;
        As[ac4 + 2][ar] = av.z;
        As[ac4 + 3][ar] = av.w;
        *reinterpret_cast<float4*>(&Bs[br][bc4]) = bv;
        __syncthreads();
        #pragma unroll
        for (int kk = 0; kk < PBK; kk++) {
            float4 a = *reinterpret_cast<const float4*>(&As[kk][ty * 4]);
            float4 b = *reinterpret_cast<const float4*>(&Bs[kk][tx * 4]);
            float ax[4] = {a.x, a.y, a.z, a.w};
            float bx[4] = {b.x, b.y, b.z, b.w};
            #pragma unroll
            for (int i = 0; i < 4; i++)
                #pragma unroll
                for (int j = 0; j < 4; j++)
                    acc[i][j] = fmaf(ax[i], bx[j], acc[i][j]);
        }
    }

    if (z == 0) {
        // q: normal row-major store [m][n]
        #pragma unroll
        for (int i = 0; i < 4; i++) {
            float4 o;
            o.x = acc[i][0]; o.y = acc[i][1]; o.z = acc[i][2]; o.w = acc[i][3];
            *reinterpret_cast<float4*>(&g_q2[(m0 + ty * 4 + i) * UNITS + n0 + tx * 4]) = o;
        }
    } else {
        // k: transpose via smem, store [b][u][s] coalesced along s
        __syncthreads();
        #pragma unroll
        for (int i = 0; i < 4; i++)
            #pragma unroll
            for (int j = 0; j < 4; j++)
                Cs[tx * 4 + j][ty * 4 + i] = acc[i][j];
        __syncthreads();
        const int b  = m0 >> 7;          // PBM=64 tiles never straddle b (128-row batches)
        const int s0 = m0 & 127;
        // 64 u-rows x 64 s: 1024 float4, 4 per thread
        #pragma unroll
        for (int r = 0; r < 4; r++) {
            int u_l = (tid >> 4) + r * 16;
            int s4  = (tid & 15) * 4;
            float4 o;
            o.x = Cs[u_l][s4 + 0];
            o.y = Cs[u_l][s4 + 1];
            o.z = Cs[u_l][s4 + 2];
            o.w = Cs[u_l][s4 + 3];
            *reinterpret_cast<float4*>(&g_k2t[((size_t)b * UNITS + n0 + u_l) * TK + s0 + s4]) = o;
        }
    }
}

// ---------------------------------------------------------------------------
// Kernel 2: scores + masked softmax + attn out.
// Grid (TQ/4, B) = (32,8) = 256 blocks, 128 threads (4 warps).
// Thread owns key s_=tid for 4 queries. k read coalesced from g_k2t.
// score = sum_u scale_u * tanh(q_u + k_u).
// ---------------------------------------------------------------------------
#define TT 4
#define NT2 128

__global__ __launch_bounds__(NT2) void score_kernel(
    const void*  __restrict__ maskp,
    const float* __restrict__ scale,
    float* __restrict__ out)
{
    __shared__ float qs[TT][UNITS];
    __shared__ float ss[UNITS];
    __shared__ float sco[TT][TK];

    const int tid = threadIdx.x;
    const int b   = blockIdx.y;
    const int t0  = blockIdx.x * TT;
    const int s_  = tid;

    // stage q rows (4 x 256 floats = 256 float4) and scale (64 float4)
    {
        const float4* q2v = reinterpret_cast<const float4*>(g_q2);
        #pragma unroll
        for (int i = 0; i < 2; i++) {
            int idx = tid + i * NT2;               // 0..255
            int t   = idx >> 6;
            int u4  = idx & 63;
            float4 v = q2v[((size_t)(b * TQ + t0 + t) * UNITS >> 2) + u4];
            *reinterpret_cast<float4*>(&qs[t][u4 * 4]) = v;
        }
        if (tid < 64)
            *reinterpret_cast<float4*>(&ss[tid * 4]) =
                reinterpret_cast<const float4*>(scale)[tid];
    }

    // mask (layout sniffed; lengths >= 64 so word 0 is a valid tag)
    const unsigned int tag = *reinterpret_cast<const unsigned int*>(maskp);
    bool valid;
    if (tag == 1u) {
        valid = reinterpret_cast<const int*>(maskp)[b * TK + s_] != 0;
    } else if (tag == 0x3f800000u) {
        valid = reinterpret_cast<const float*>(maskp)[b * TK + s_] != 0.0f;
    } else {
        valid = reinterpret_cast<const unsigned char*>(maskp)[b * TK + s_] != 0;
    }
    __syncthreads();

    const float* kp = g_k2t + (size_t)b * UNITS * TK + s_;

    float a0 = 0.f, a1 = 0.f, a2 = 0.f, a3 = 0.f;

    float pre[8];
    #pragma unroll
    for (int i = 0; i < 8; i++) pre[i] = __ldg(kp + i * TK);

    for (int u0 = 0; u0 < UNITS; u0 += 8) {
        float cur[8];
        #pragma unroll
        for (int i = 0; i < 8; i++) cur[i] = pre[i];
        if (u0 + 8 < UNITS) {
            #pragma unroll
            for (int i = 0; i < 8; i++) pre[i] = __ldg(kp + (u0 + 8 + i) * TK);
        }
        #pragma unroll
        for (int i = 0; i < 8; i++) {
            float kv = cur[i];
            float sv = ss[u0 + i];
            a0 = fmaf(sv, tanha(qs[0][u0 + i] + kv), a0);
            a1 = fmaf(sv, tanha(qs[1][u0 + i] + kv), a1);
            a2 = fmaf(sv, tanha(qs[2][u0 + i] + kv), a2);
            a3 = fmaf(sv, tanha(qs[3][u0 + i] + kv), a3);
        }
    }

    sco[0][s_] = valid ? a0 : -1e9f;
    sco[1][s_] = valid ? a1 : -1e9f;
    sco[2][s_] = valid ? a2 : -1e9f;
    sco[3][s_] = valid ? a3 : -1e9f;
    __syncthreads();

    // masked softmax: warp w handles query row w
    const int wid  = tid >> 5;
    const int lane = tid & 31;
    {
        float v0 = sco[wid][lane +  0];
        float v1 = sco[wid][lane + 32];
        float v2 = sco[wid][lane + 64];
        float v3 = sco[wid][lane + 96];
        float m = fmaxf(fmaxf(v0, v1), fmaxf(v2, v3));
        #pragma unroll
        for (int o = 16; o; o >>= 1) m = fmaxf(m, __shfl_xor_sync(0xffffffffu, m, o));
        float e0 = __expf(v0 - m), e1 = __expf(v1 - m);
        float e2 = __expf(v2 - m), e3 = __expf(v3 - m);
        float s = e0 + e1 + e2 + e3;
        #pragma unroll
        for (int o = 16; o; o >>= 1) s += __shfl_xor_sync(0xffffffffu, s, o);
        float inv = 1.0f / s;
        e0 *= inv; e1 *= inv; e2 *= inv; e3 *= inv;
        float* aout = out + (size_t)BB * TQ * NH + (size_t)(b * TQ + t0 + wid) * TK;
        aout[lane +  0] = e0;
        aout[lane + 32] = e1;
        aout[lane + 64] = e2;
        aout[lane + 96] = e3;
    }
}

// ---------------------------------------------------------------------------
// Kernel 3: context = attn @ value.
// Grid (NH/128, TQ/16, B) = (4,8,8) = 256 blocks, 128 threads.
// Block: 16 queries x 128 features. attn staged in smem [s][t], row stride
// 20 floats (80 B) so &a_s[s][4*j] is always 16B-aligned for float4 reads.
// ---------------------------------------------------------------------------
#define CTT 16
#define CTP 20   // padded row stride (16B-aligned rows, conflict-spread)

__global__ __launch_bounds__(128) void context_kernel(
    const float* __restrict__ value,
    const float* __restrict__ out_attn,   // attn section of out
    float* __restrict__ out)
{
    __shared__ __align__(16) float a_s[TK][CTP];

    const int tid = threadIdx.x;
    const int h   = blockIdx.x * 128 + tid;
    const int t0  = blockIdx.y * CTT;
    const int b   = blockIdx.z;

    // stage attn[b][t0..t0+15][:] -> a_s[s][t]
    #pragma unroll
    for (int i = 0; i < CTT; i++) {
        int idx = tid + i * 128;                  // 0..2047
        int t = idx >> 7;
        int s = idx & 127;
        a_s[s][t] = out_attn[(size_t)(b * TQ + t0 + t) * TK + s];
    }
    __syncthreads();

    float acc[CTT] = {};
    const float* vb = value + (size_t)b * TK * NH + h;
    #pragma unroll 4
    for (int s = 0; s < TK; s++) {
        float v = __ldg(vb + (size_t)s * NH);
        #pragma unroll
        for (int t4 = 0; t4 < CTT; t4 += 4) {
            float4 w = *reinterpret_cast<const float4*>(&a_s[s][t4]);
            acc[t4 + 0] = fmaf(w.x, v, acc[t4 + 0]);
            acc[t4 + 1] = fmaf(w.y, v, acc[t4 + 1]);
            acc[t4 + 2] = fmaf(w.z, v, acc[t4 + 2]);
            acc[t4 + 3] = fmaf(w.w, v, acc[t4 + 3]);
        }
    }
    #pragma unroll
    for (int t = 0; t < CTT; t++)
        out[(size_t)(b * TQ + t0 + t) * NH + h] = acc[t];
}

// ---------------------------------------------------------------------------
extern "C" void kernel_launch(void* const* d_in, const int* in_sizes, int n_in,
                              void* d_out, int out_size)
{
    const float* query = (const float*)d_in[0];   // (B,TQ,NH)
    const float* value = (const float*)d_in[1];   // (B,TK,NH)
    const void*  mask  = d_in[2];                 // (B,TK) bool (layout sniffed)
    const float* W1    = (const float*)d_in[3];   // (NH,UNITS)
    const float* W2    = (const float*)d_in[4];   // (NH,UNITS)
    const float* scale = (const float*)d_in[5];   // (UNITS,)
    float* out = (float*)d_out;                   // [context | attn]

    dim3 g1(UNITS / PBN, (BB * TQ) / PBM, 2);     // (4,16,2)
    proj_kernel<<<g1, 256>>>(query, value, W1, W2);

    dim3 g2(TQ / TT, BB);                         // (32,8)
    score_kernel<<<g2, NT2>>>(mask, scale, out);

    const float* attn_sec = out + (size_t)BB * TQ * NH;
    dim3 g3(NH / 128, TQ / CTT, BB);              // (4,8,8)
    context_kernel<<<g3, 128>>>(value, attn_sec, out);
}

// round 5
// speedup vs baseline: 1.2733x; 1.1147x over previous
#include <cuda_runtime.h>
#include <cstdint>

#define BB 8
#define TQ 128
#define TK 128
#define NH 512
#define UNITS 256

// scratch (allocation-free rule: device globals)
__device__ float g_q2[BB * TQ * UNITS];          // [b][t][u]
__device__ float g_k2t[BB * UNITS * TK];         // [b][u][s]  (transposed!)

__device__ __forceinline__ float tanha(float x) {
    float y; asm("tanh.approx.f32 %0, %1;" : "=f"(y) : "f"(x)); return y;
}

// ---------------------------------------------------------------------------
// Kernel 1: projections.  q = query@W1 -> g_q2 [b][t][u]
//                         k = value@W2 -> g_k2t [b][u][s] (transposed store)
// M = 1024 (B*T), K = 512 (NH), N = 256 (UNITS). 64x64 tile, 4x4/thread.
// Double-buffered smem, ONE barrier per BK=16 step, prefetch LDG issued
// before the compute phase so global latency hides under the FFMA block.
// ---------------------------------------------------------------------------
#define PBM 64
#define PBN 64
#define PBK 16

__global__ __launch_bounds__(256) void proj_kernel(
    const float* __restrict__ Q, const float* __restrict__ V,
    const float* __restrict__ W1, const float* __restrict__ W2)
{
    const int z = blockIdx.z;
    const float* __restrict__ X = z ? V : Q;
    const float* __restrict__ W = z ? W2 : W1;

    __shared__ float As[2][PBK][PBM];
    __shared__ float Bs[2][PBK][PBN + 4];
    __shared__ float Cs[PBN][PBM + 1];   // transpose staging (z==1 only)

    const int tid = threadIdx.x;
    const int tx = tid & 15;
    const int ty = tid >> 4;
    const int m0 = blockIdx.y * PBM;
    const int n0 = blockIdx.x * PBN;

    const int ar  = tid >> 2;            // 0..63
    const int ac4 = (tid & 3) << 2;      // 0,4,8,12
    const int br  = tid >> 4;            // 0..15
    const int bc4 = (tid & 15) << 2;     // 0..60

    const float* __restrict__ Xp = &X[(m0 + ar) * NH + ac4];
    const float* __restrict__ Wp = &W[br * UNITS + n0 + bc4];

    float acc[4][4] = {};

    // helper lambdas (inlined)
    auto STAGE = [&](int buf, float4 av, float4 bv) {
        As[buf][ac4 + 0][ar] = av.x;
        As[buf][ac4 + 1][ar] = av.y;
        As[buf][ac4 + 2][ar] = av.z;
        As[buf][ac4 + 3][ar] = av.w;
        *reinterpret_cast<float4*>(&Bs[buf][br][bc4]) = bv;
    };

    // preload tile 0 into buffer 0
    {
        float4 av = *reinterpret_cast<const float4*>(Xp);
        float4 bv = *reinterpret_cast<const float4*>(Wp);
        STAGE(0, av, bv);
    }
    __syncthreads();

    #define COMPUTE(buf)                                                      \
        _Pragma("unroll")                                                     \
        for (int kk = 0; kk < PBK; kk++) {                                    \
            float4 a = *reinterpret_cast<const float4*>(&As[buf][kk][ty * 4]);\
            float4 b = *reinterpret_cast<const float4*>(&Bs[buf][kk][tx * 4]);\
            float ax[4] = {a.x, a.y, a.z, a.w};                               \
            float bx[4] = {b.x, b.y, b.z, b.w};                               \
            _Pragma("unroll")                                                 \
            for (int i = 0; i < 4; i++)                                       \
                _Pragma("unroll")                                             \
                for (int j = 0; j < 4; j++)                                   \
                    acc[i][j] = fmaf(ax[i], bx[j], acc[i][j]);                \
        }

    #pragma unroll 1
    for (int k0 = 0; k0 < NH; k0 += 2 * PBK) {
        // phase 0: prefetch (k0+PBK) early, compute buf0, stage into buf1
        float4 av = *reinterpret_cast<const float4*>(Xp + (k0 + PBK));
        float4 bv = *reinterpret_cast<const float4*>(Wp + (size_t)(k0 + PBK) * UNITS);
        COMPUTE(0);
        STAGE(1, av, bv);
        __syncthreads();

        // phase 1: prefetch (k0+2*PBK) if any, compute buf1, stage into buf0
        const bool more = (k0 + 2 * PBK) < NH;
        float4 av2, bv2;
        if (more) {
            av2 = *reinterpret_cast<const float4*>(Xp + (k0 + 2 * PBK));
            bv2 = *reinterpret_cast<const float4*>(Wp + (size_t)(k0 + 2 * PBK) * UNITS);
        }
        COMPUTE(1);
        if (more) STAGE(0, av2, bv2);
        __syncthreads();
    }
    #undef COMPUTE

    if (z == 0) {
        // q: normal row-major store [m][n]
        #pragma unroll
        for (int i = 0; i < 4; i++) {
            float4 o;
            o.x = acc[i][0]; o.y = acc[i][1]; o.z = acc[i][2]; o.w = acc[i][3];
            *reinterpret_cast<float4*>(&g_q2[(m0 + ty * 4 + i) * UNITS + n0 + tx * 4]) = o;
        }
    } else {
        // k: transpose via smem, store [b][u][s] coalesced along s
        #pragma unroll
        for (int i = 0; i < 4; i++)
            #pragma unroll
            for (int j = 0; j < 4; j++)
                Cs[tx * 4 + j][ty * 4 + i] = acc[i][j];
        __syncthreads();
        const int b  = m0 >> 7;          // PBM=64 tiles never straddle b
        const int s0 = m0 & 127;
        #pragma unroll
        for (int r = 0; r < 4; r++) {
            int u_l = (tid >> 4) + r * 16;
            int s4  = (tid & 15) * 4;
            float4 o;
            o.x = Cs[u_l][s4 + 0];
            o.y = Cs[u_l][s4 + 1];
            o.z = Cs[u_l][s4 + 2];
            o.w = Cs[u_l][s4 + 3];
            *reinterpret_cast<float4*>(&g_k2t[((size_t)b * UNITS + n0 + u_l) * TK + s0 + s4]) = o;
        }
    }
}

// ---------------------------------------------------------------------------
// Kernel 2: scores + masked softmax + attn out.
// Grid (TQ/4, B) = (32,8) = 256 blocks, 128 threads (4 warps).
// Thread owns key s_=tid for 4 queries. k read coalesced from g_k2t.
// score = sum_u scale_u * tanh(q_u + k_u).
// ---------------------------------------------------------------------------
#define TT 4
#define NT2 128

__global__ __launch_bounds__(NT2) void score_kernel(
    const void*  __restrict__ maskp,
    const float* __restrict__ scale,
    float* __restrict__ out)
{
    __shared__ float qs[TT][UNITS];
    __shared__ float ss[UNITS];
    __shared__ float sco[TT][TK];

    const int tid = threadIdx.x;
    const int b   = blockIdx.y;
    const int t0  = blockIdx.x * TT;
    const int s_  = tid;

    // stage q rows (4 x 256 floats) and scale
    {
        const float4* q2v = reinterpret_cast<const float4*>(g_q2);
        #pragma unroll
        for (int i = 0; i < 2; i++) {
            int idx = tid + i * NT2;               // 0..255
            int t   = idx >> 6;
            int u4  = idx & 63;
            float4 v = q2v[((size_t)(b * TQ + t0 + t) * UNITS >> 2) + u4];
            *reinterpret_cast<float4*>(&qs[t][u4 * 4]) = v;
        }
        if (tid < 64)
            *reinterpret_cast<float4*>(&ss[tid * 4]) =
                reinterpret_cast<const float4*>(scale)[tid];
    }

    // mask (layout sniffed; lengths >= 64 so word 0 is a valid tag)
    const unsigned int tag = *reinterpret_cast<const unsigned int*>(maskp);
    bool valid;
    if (tag == 1u) {
        valid = reinterpret_cast<const int*>(maskp)[b * TK + s_] != 0;
    } else if (tag == 0x3f800000u) {
        valid = reinterpret_cast<const float*>(maskp)[b * TK + s_] != 0.0f;
    } else {
        valid = reinterpret_cast<const unsigned char*>(maskp)[b * TK + s_] != 0;
    }
    __syncthreads();

    const float* kp = g_k2t + (size_t)b * UNITS * TK + s_;

    float a0 = 0.f, a1 = 0.f, a2 = 0.f, a3 = 0.f;

    float pre[8];
    #pragma unroll
    for (int i = 0; i < 8; i++) pre[i] = __ldg(kp + i * TK);

    for (int u0 = 0; u0 < UNITS; u0 += 8) {
        float cur[8];
        #pragma unroll
        for (int i = 0; i < 8; i++) cur[i] = pre[i];
        if (u0 + 8 < UNITS) {
            #pragma unroll
            for (int i = 0; i < 8; i++) pre[i] = __ldg(kp + (u0 + 8 + i) * TK);
        }
        #pragma unroll
        for (int i = 0; i < 8; i++) {
            float kv = cur[i];
            float sv = ss[u0 + i];
            a0 = fmaf(sv, tanha(qs[0][u0 + i] + kv), a0);
            a1 = fmaf(sv, tanha(qs[1][u0 + i] + kv), a1);
            a2 = fmaf(sv, tanha(qs[2][u0 + i] + kv), a2);
            a3 = fmaf(sv, tanha(qs[3][u0 + i] + kv), a3);
        }
    }

    sco[0][s_] = valid ? a0 : -1e9f;
    sco[1][s_] = valid ? a1 : -1e9f;
    sco[2][s_] = valid ? a2 : -1e9f;
    sco[3][s_] = valid ? a3 : -1e9f;
    __syncthreads();

    // masked softmax: warp w handles query row w
    const int wid  = tid >> 5;
    const int lane = tid & 31;
    {
        float v0 = sco[wid][lane +  0];
        float v1 = sco[wid][lane + 32];
        float v2 = sco[wid][lane + 64];
        float v3 = sco[wid][lane + 96];
        float m = fmaxf(fmaxf(v0, v1), fmaxf(v2, v3));
        #pragma unroll
        for (int o = 16; o; o >>= 1) m = fmaxf(m, __shfl_xor_sync(0xffffffffu, m, o));
        float e0 = __expf(v0 - m), e1 = __expf(v1 - m);
        float e2 = __expf(v2 - m), e3 = __expf(v3 - m);
        float s = e0 + e1 + e2 + e3;
        #pragma unroll
        for (int o = 16; o; o >>= 1) s += __shfl_xor_sync(0xffffffffu, s, o);
        float inv = 1.0f / s;
        e0 *= inv; e1 *= inv; e2 *= inv; e3 *= inv;
        float* aout = out + (size_t)BB * TQ * NH + (size_t)(b * TQ + t0 + wid) * TK;
        aout[lane +  0] = e0;
        aout[lane + 32] = e1;
        aout[lane + 64] = e2;
        aout[lane + 96] = e3;
    }
}

// ---------------------------------------------------------------------------
// Kernel 3: context = attn @ value.
// Grid (NH/128, TQ/16, B) = (4,8,8) = 256 blocks, 128 threads.
// ---------------------------------------------------------------------------
#define CTT 16
#define CTP 20   // padded row stride (16B-aligned rows)

__global__ __launch_bounds__(128) void context_kernel(
    const float* __restrict__ value,
    const float* __restrict__ out_attn,   // attn section of out
    float* __restrict__ out)
{
    __shared__ __align__(16) float a_s[TK][CTP];

    const int tid = threadIdx.x;
    const int h   = blockIdx.x * 128 + tid;
    const int t0  = blockIdx.y * CTT;
    const int b   = blockIdx.z;

    #pragma unroll
    for (int i = 0; i < CTT; i++) {
        int idx = tid + i * 128;
        int t = idx >> 7;
        int s = idx & 127;
        a_s[s][t] = out_attn[(size_t)(b * TQ + t0 + t) * TK + s];
    }
    __syncthreads();

    float acc[CTT] = {};
    const float* vb = value + (size_t)b * TK * NH + h;
    #pragma unroll 4
    for (int s = 0; s < TK; s++) {
        float v = __ldg(vb + (size_t)s * NH);
        #pragma unroll
        for (int t4 = 0; t4 < CTT; t4 += 4) {
            float4 w = *reinterpret_cast<const float4*>(&a_s[s][t4]);
            acc[t4 + 0] = fmaf(w.x, v, acc[t4 + 0]);
            acc[t4 + 1] = fmaf(w.y, v, acc[t4 + 1]);
            acc[t4 + 2] = fmaf(w.z, v, acc[t4 + 2]);
            acc[t4 + 3] = fmaf(w.w, v, acc[t4 + 3]);
        }
    }
    #pragma unroll
    for (int t = 0; t < CTT; t++)
        out[(size_t)(b * TQ + t0 + t) * NH + h] = acc[t];
}

// ---------------------------------------------------------------------------
extern "C" void kernel_launch(void* const* d_in, const int* in_sizes, int n_in,
                              void* d_out, int out_size)
{
    const float* query = (const float*)d_in[0];   // (B,TQ,NH)
    const float* value = (const float*)d_in[1];   // (B,TK,NH)
    const void*  mask  = d_in[2];                 // (B,TK) bool (layout sniffed)
    const float* W1    = (const float*)d_in[3];   // (NH,UNITS)
    const float* W2    = (const float*)d_in[4];   // (NH,UNITS)
    const float* scale = (const float*)d_in[5];   // (UNITS,)
    float* out = (float*)d_out;                   // [context | attn]

    dim3 g1(UNITS / PBN, (BB * TQ) / PBM, 2);     // (4,16,2)
    proj_kernel<<<g1, 256>>>(query, value, W1, W2);

    dim3 g2(TQ / TT, BB);                         // (32,8)
    score_kernel<<<g2, NT2>>>(mask, scale, out);

    const float* attn_sec = out + (size_t)BB * TQ * NH;
    dim3 g3(NH / 128, TQ / CTT, BB);              // (4,8,8)
    context_kernel<<<g3, 128>>>(value, attn_sec, out);
}

// round 6
// speedup vs baseline: 1.3258x; 1.0413x over previous
#include <cuda_runtime.h>
#include <cuda_bf16.h>
#include <mma.h>
#include <cstdint>

using namespace nvcuda;

#define BB 8
#define TQ 128
#define TK 128
#define NH 512
#define UNITS 256

// scratch (allocation-free rule: device globals)
__device__ float g_q2[BB * TQ * UNITS];          // [b][t][u]
__device__ float g_k2t[BB * UNITS * TK];         // [b][u][s]  (transposed)

__device__ __forceinline__ float tanha(float x) {
    float y; asm("tanh.approx.f32 %0, %1;" : "=f"(y) : "f"(x)); return y;
}

// ---------------------------------------------------------------------------
// Kernel 1: projections on TENSOR CORES (wmma bf16 hi/lo split, ~fp32 acc).
//   z=0: q = query@W1 -> g_q2 [b][t][u]      (row-major store)
//   z=1: k = value@W2 -> g_k2t [b][u][s]     (col-major store = free transpose)
// Block tile 64x64, BK=32, 256 threads (8 warps: 2m x 4n, warp tile 32x16).
// C ~= Xhi*Whi + Xhi*Wlo + Xlo*Whi   (lo*lo dropped, ~2^-17 rel err)
// ---------------------------------------------------------------------------
#define GBM 64
#define GBN 64
#define GBK 32
#define XLD 40    // bf16 row stride (mult of 8)
#define WLD 72

__global__ __launch_bounds__(256) void proj_kernel(
    const float* __restrict__ Q, const float* __restrict__ V,
    const float* __restrict__ W1, const float* __restrict__ W2)
{
    const int z = blockIdx.z;
    const float* __restrict__ X = z ? V : Q;
    const float* __restrict__ W = z ? W2 : W1;

    __shared__ __nv_bfloat16 Xhi[2][GBM][XLD];
    __shared__ __nv_bfloat16 Xlo[2][GBM][XLD];
    __shared__ __nv_bfloat16 Whi[2][GBK][WLD];
    __shared__ __nv_bfloat16 Wlo[2][GBK][WLD];

    const int tid = threadIdx.x;
    const int m0 = blockIdx.y * GBM;
    const int n0 = blockIdx.x * GBN;

    // staging maps: X tile 64x32 (8 floats/thread), W tile 32x64 (8/thread)
    const int xr = tid >> 2;              // 0..63
    const int xk = (tid & 3) * 8;         // 0,8,16,24
    const int wr = tid >> 3;              // 0..31
    const int wn = (tid & 7) * 8;         // 0..56

    const float* __restrict__ Xp = &X[(m0 + xr) * NH + xk];
    const float* __restrict__ Wp = &W[wr * UNITS + n0 + wn];

    // warp layout: 2 (m) x 4 (n); warp tile 32x16
    const int w   = tid >> 5;
    const int wm  = (w & 1) * 32;
    const int wnn = (w >> 1) * 16;

    wmma::fragment<wmma::accumulator, 16, 16, 16, float> cfrag[2];
    wmma::fill_fragment(cfrag[0], 0.0f);
    wmma::fill_fragment(cfrag[1], 0.0f);

    // convert 8 floats -> hi/lo bf16 pairs and store to smem
    auto STAGE = [&](int buf, const float4 xa, const float4 xb,
                               const float4 wa, const float4 wb) {
        const float xf[8] = {xa.x, xa.y, xa.z, xa.w, xb.x, xb.y, xb.z, xb.w};
        const float wf[8] = {wa.x, wa.y, wa.z, wa.w, wb.x, wb.y, wb.z, wb.w};
        #pragma unroll
        for (int j = 0; j < 4; j++) {
            __nv_bfloat162 h = __floats2bfloat162_rn(xf[2*j], xf[2*j+1]);
            __nv_bfloat162 l = __floats2bfloat162_rn(
                xf[2*j]   - __bfloat162float(__low2bfloat16(h)),
                xf[2*j+1] - __bfloat162float(__high2bfloat16(h)));
            *reinterpret_cast<__nv_bfloat162*>(&Xhi[buf][xr][xk + 2*j]) = h;
            *reinterpret_cast<__nv_bfloat162*>(&Xlo[buf][xr][xk + 2*j]) = l;
        }
        #pragma unroll
        for (int j = 0; j < 4; j++) {
            __nv_bfloat162 h = __floats2bfloat162_rn(wf[2*j], wf[2*j+1]);
            __nv_bfloat162 l = __floats2bfloat162_rn(
                wf[2*j]   - __bfloat162float(__low2bfloat16(h)),
                wf[2*j+1] - __bfloat162float(__high2bfloat16(h)));
            *reinterpret_cast<__nv_bfloat162*>(&Whi[buf][wr][wn + 2*j]) = h;
            *reinterpret_cast<__nv_bfloat162*>(&Wlo[buf][wr][wn + 2*j]) = l;
        }
    };

    // preload tile 0
    {
        float4 xa = *reinterpret_cast<const float4*>(Xp);
        float4 xb = *reinterpret_cast<const float4*>(Xp + 4);
        float4 wa = *reinterpret_cast<const float4*>(Wp);
        float4 wb = *reinterpret_cast<const float4*>(Wp + 4);
        STAGE(0, xa, xb, wa, wb);
    }
    __syncthreads();

    const int NIT = NH / GBK;             // 16
    #pragma unroll 1
    for (int it = 0; it < NIT; it++) {
        const int buf = it & 1;
        const bool more = (it + 1) < NIT;
        float4 xa, xb, wa, wb;
        if (more) {                        // issue LDGs early
            const int ko = (it + 1) * GBK;
            xa = *reinterpret_cast<const float4*>(Xp + ko);
            xb = *reinterpret_cast<const float4*>(Xp + ko + 4);
            wa = *reinterpret_cast<const float4*>(Wp + (size_t)ko * UNITS);
            wb = *reinterpret_cast<const float4*>(Wp + (size_t)ko * UNITS + 4);
        }

        #pragma unroll
        for (int ks = 0; ks < GBK; ks += 16) {
            wmma::fragment<wmma::matrix_a, 16, 16, 16, __nv_bfloat16, wmma::row_major> ah[2], al[2];
            wmma::fragment<wmma::matrix_b, 16, 16, 16, __nv_bfloat16, wmma::row_major> bh, bl;
            wmma::load_matrix_sync(ah[0], &Xhi[buf][wm +  0][ks], XLD);
            wmma::load_matrix_sync(ah[1], &Xhi[buf][wm + 16][ks], XLD);
            wmma::load_matrix_sync(al[0], &Xlo[buf][wm +  0][ks], XLD);
            wmma::load_matrix_sync(al[1], &Xlo[buf][wm + 16][ks], XLD);
            wmma::load_matrix_sync(bh, &Whi[buf][ks][wnn], WLD);
            wmma::load_matrix_sync(bl, &Wlo[buf][ks][wnn], WLD);
            #pragma unroll
            for (int i = 0; i < 2; i++) {
                wmma::mma_sync(cfrag[i], ah[i], bh, cfrag[i]);
                wmma::mma_sync(cfrag[i], ah[i], bl, cfrag[i]);
                wmma::mma_sync(cfrag[i], al[i], bh, cfrag[i]);
            }
        }

        if (more) STAGE(buf ^ 1, xa, xb, wa, wb);
        __syncthreads();
    }

    if (z == 0) {
        // q: row-major [m][u]
        #pragma unroll
        for (int i = 0; i < 2; i++) {
            float* p = &g_q2[(size_t)(m0 + wm + i * 16) * UNITS + n0 + wnn];
            wmma::store_matrix_sync(p, cfrag[i], UNITS, wmma::mem_row_major);
        }
    } else {
        // k: col-major store = direct transposed layout [b][u][s]
        const int b  = m0 >> 7;           // 64-row tiles never straddle a batch
        const int s0 = m0 & 127;
        #pragma unroll
        for (int i = 0; i < 2; i++) {
            float* p = &g_k2t[((size_t)b * UNITS + n0 + wnn) * TK + s0 + wm + i * 16];
            wmma::store_matrix_sync(p, cfrag[i], TK, wmma::mem_col_major);
        }
    }
}

// ---------------------------------------------------------------------------
// Kernel 2: scores + masked softmax + attn out.
// Grid (TQ/4, B) = (32,8) = 256 blocks, 128 threads (4 warps).
// Thread owns key s_=tid for 4 queries. k read coalesced from g_k2t.
// score = sum_u scale_u * tanh(q_u + k_u).
// ---------------------------------------------------------------------------
#define TT 4
#define NT2 128

__global__ __launch_bounds__(NT2) void score_kernel(
    const void*  __restrict__ maskp,
    const float* __restrict__ scale,
    float* __restrict__ out)
{
    __shared__ float qs[TT][UNITS];
    __shared__ float ss[UNITS];
    __shared__ float sco[TT][TK];

    const int tid = threadIdx.x;
    const int b   = blockIdx.y;
    const int t0  = blockIdx.x * TT;
    const int s_  = tid;

    // stage q rows (4 x 256 floats) and scale
    {
        const float4* q2v = reinterpret_cast<const float4*>(g_q2);
        #pragma unroll
        for (int i = 0; i < 2; i++) {
            int idx = tid + i * NT2;               // 0..255
            int t   = idx >> 6;
            int u4  = idx & 63;
            float4 v = q2v[((size_t)(b * TQ + t0 + t) * UNITS >> 2) + u4];
            *reinterpret_cast<float4*>(&qs[t][u4 * 4]) = v;
        }
        if (tid < 64)
            *reinterpret_cast<float4*>(&ss[tid * 4]) =
                reinterpret_cast<const float4*>(scale)[tid];
    }

    // mask (layout sniffed; lengths >= 64 so word 0 is a valid tag)
    const unsigned int tag = *reinterpret_cast<const unsigned int*>(maskp);
    bool valid;
    if (tag == 1u) {
        valid = reinterpret_cast<const int*>(maskp)[b * TK + s_] != 0;
    } else if (tag == 0x3f800000u) {
        valid = reinterpret_cast<const float*>(maskp)[b * TK + s_] != 0.0f;
    } else {
        valid = reinterpret_cast<const unsigned char*>(maskp)[b * TK + s_] != 0;
    }
    __syncthreads();

    const float* kp = g_k2t + (size_t)b * UNITS * TK + s_;

    float a0 = 0.f, a1 = 0.f, a2 = 0.f, a3 = 0.f;

    float pre[8];
    #pragma unroll
    for (int i = 0; i < 8; i++) pre[i] = __ldg(kp + i * TK);

    for (int u0 = 0; u0 < UNITS; u0 += 8) {
        float cur[8];
        #pragma unroll
        for (int i = 0; i < 8; i++) cur[i] = pre[i];
        if (u0 + 8 < UNITS) {
            #pragma unroll
            for (int i = 0; i < 8; i++) pre[i] = __ldg(kp + (u0 + 8 + i) * TK);
        }
        #pragma unroll
        for (int i = 0; i < 8; i++) {
            float kv = cur[i];
            float sv = ss[u0 + i];
            a0 = fmaf(sv, tanha(qs[0][u0 + i] + kv), a0);
            a1 = fmaf(sv, tanha(qs[1][u0 + i] + kv), a1);
            a2 = fmaf(sv, tanha(qs[2][u0 + i] + kv), a2);
            a3 = fmaf(sv, tanha(qs[3][u0 + i] + kv), a3);
        }
    }

    sco[0][s_] = valid ? a0 : -1e9f;
    sco[1][s_] = valid ? a1 : -1e9f;
    sco[2][s_] = valid ? a2 : -1e9f;
    sco[3][s_] = valid ? a3 : -1e9f;
    __syncthreads();

    // masked softmax: warp w handles query row w
    const int wid  = tid >> 5;
    const int lane = tid & 31;
    {
        float v0 = sco[wid][lane +  0];
        float v1 = sco[wid][lane + 32];
        float v2 = sco[wid][lane + 64];
        float v3 = sco[wid][lane + 96];
        float m = fmaxf(fmaxf(v0, v1), fmaxf(v2, v3));
        #pragma unroll
        for (int o = 16; o; o >>= 1) m = fmaxf(m, __shfl_xor_sync(0xffffffffu, m, o));
        float e0 = __expf(v0 - m), e1 = __expf(v1 - m);
        float e2 = __expf(v2 - m), e3 = __expf(v3 - m);
        float s = e0 + e1 + e2 + e3;
        #pragma unroll
        for (int o = 16; o; o >>= 1) s += __shfl_xor_sync(0xffffffffu, s, o);
        float inv = 1.0f / s;
        e0 *= inv; e1 *= inv; e2 *= inv; e3 *= inv;
        float* aout = out + (size_t)BB * TQ * NH + (size_t)(b * TQ + t0 + wid) * TK;
        aout[lane +  0] = e0;
        aout[lane + 32] = e1;
        aout[lane + 64] = e2;
        aout[lane + 96] = e3;
    }
}

// ---------------------------------------------------------------------------
// Kernel 3: context = attn @ value.
// Grid (NH/128, TQ/16, B) = (4,8,8) = 256 blocks, 128 threads.
// ---------------------------------------------------------------------------
#define CTT 16
#define CTP 20   // padded row stride (16B-aligned rows)

__global__ __launch_bounds__(128) void context_kernel(
    const float* __restrict__ value,
    const float* __restrict__ out_attn,   // attn section of out
    float* __restrict__ out)
{
    __shared__ __align__(16) float a_s[TK][CTP];

    const int tid = threadIdx.x;
    const int h   = blockIdx.x * 128 + tid;
    const int t0  = blockIdx.y * CTT;
    const int b   = blockIdx.z;

    #pragma unroll
    for (int i = 0; i < CTT; i++) {
        int idx = tid + i * 128;
        int t = idx >> 7;
        int s = idx & 127;
        a_s[s][t] = out_attn[(size_t)(b * TQ + t0 + t) * TK + s];
    }
    __syncthreads();

    float acc[CTT] = {};
    const float* vb = value + (size_t)b * TK * NH + h;
    #pragma unroll 4
    for (int s = 0; s < TK; s++) {
        float v = __ldg(vb + (size_t)s * NH);
        #pragma unroll
        for (int t4 = 0; t4 < CTT; t4 += 4) {
            float4 w = *reinterpret_cast<const float4*>(&a_s[s][t4]);
            acc[t4 + 0] = fmaf(w.x, v, acc[t4 + 0]);
            acc[t4 + 1] = fmaf(w.y, v, acc[t4 + 1]);
            acc[t4 + 2] = fmaf(w.z, v, acc[t4 + 2]);
            acc[t4 + 3] = fmaf(w.w, v, acc[t4 + 3]);
        }
    }
    #pragma unroll
    for (int t = 0; t < CTT; t++)
        out[(size_t)(b * TQ + t0 + t) * NH + h] = acc[t];
}

// ---------------------------------------------------------------------------
extern "C" void kernel_launch(void* const* d_in, const int* in_sizes, int n_in,
                              void* d_out, int out_size)
{
    const float* query = (const float*)d_in[0];   // (B,TQ,NH)
    const float* value = (const float*)d_in[1];   // (B,TK,NH)
    const void*  mask  = d_in[2];                 // (B,TK) bool (layout sniffed)
    const float* W1    = (const float*)d_in[3];   // (NH,UNITS)
    const float* W2    = (const float*)d_in[4];   // (NH,UNITS)
    const float* scale = (const float*)d_in[5];   // (UNITS,)
    float* out = (float*)d_out;                   // [context | attn]

    dim3 g1(UNITS / GBN, (BB * TQ) / GBM, 2);     // (4,16,2) = 128 blocks
    proj_kernel<<<g1, 256>>>(query, value, W1, W2);

    dim3 g2(TQ / TT, BB);                         // (32,8)
    score_kernel<<<g2, NT2>>>(mask, scale, out);

    const float* attn_sec = out + (size_t)BB * TQ * NH;
    dim3 g3(NH / 128, TQ / CTT, BB);              // (4,8,8)
    context_kernel<<<g3, 128>>>(value, attn_sec, out);
}